// round 3
// baseline (speedup 1.0000x reference)
#include <cuda_runtime.h>
#include <cuda_bf16.h>

// LearnableEMA: y[b,0,:] = x[b,0,:]; y[b,t,:] = a*y[b,t-1,:] + (1-a)*x[b,t,:]
// a = clip(sigmoid(logit_alpha), 1e-4, 1-1e-4), per channel.
//
// Decoupled-lookback scan, fully float4-vectorized:
//  - block = (b, chunk of TC=16 timesteps, all 512 channels), 128 thr x float4
//  - LDG.128 / STG.128 streaming, 4 independent FMA chains per thread
//  - batched lookback: K predecessor flags polled concurrently, K aggregate
//    loads issued as independent MLP, plus a generic residual walk.

#define Bn 16
#define Tn 4096
#define Cn 512
#define TC 16             // chunk length along T
#define NC (Tn / TC)      // 256 chunks
#define CB 128            // threads (each owns 4 channels)
#define NBLK (Bn * NC)    // 4096 blocks
#define KMAX 16           // batched lookback depth
#define ROWS4 (Cn / 4)    // float4s per row = 128

// Lookback state (device globals: no allocation allowed).
__device__ float4       g_L4[Bn * NC * ROWS4];  // chunk aggregates (zero carry-in)
__device__ unsigned int g_flag[Bn * NC];        // == epoch+1 when aggregate ready
__device__ unsigned int g_ticket;               // monotone across graph replays

__device__ __forceinline__ float4 f4mul(float4 u, float4 v) {
    return make_float4(u.x*v.x, u.y*v.y, u.z*v.z, u.w*v.w);
}
__device__ __forceinline__ float4 f4fma(float4 a, float4 b, float4 c) {
    return make_float4(fmaf(a.x,b.x,c.x), fmaf(a.y,b.y,c.y),
                       fmaf(a.z,b.z,c.z), fmaf(a.w,b.w,c.w));
}

__global__ __launch_bounds__(CB, 4) void ema_scan_kernel(
    const float* __restrict__ x,
    const float* __restrict__ logit_alpha,
    float* __restrict__ y)
{
    __shared__ unsigned int s_raw;

    // Ticket: virtual block id in scheduling order (chunk index outermost)
    // => a block only waits on blocks with earlier tickets (resident/retired).
    if (threadIdx.x == 0) s_raw = atomicAdd(&g_ticket, 1u);
    __syncthreads();
    const unsigned int raw   = s_raw;
    const unsigned int epoch = raw / NBLK;
    const unsigned int vbid  = raw % NBLK;
    const unsigned int ready = epoch + 1u;

    const int j = (int)(vbid / Bn);   // chunk index (outermost in ticket order)
    const int b = (int)(vbid % Bn);
    const int c4 = threadIdx.x;       // float4 channel-group index

    // Per-channel alpha (4 channels per thread)
    const float4 lav = ((const float4*)logit_alpha)[c4];
    float4 a;
    a.x = 1.0f / (1.0f + expf(-lav.x));
    a.y = 1.0f / (1.0f + expf(-lav.y));
    a.z = 1.0f / (1.0f + expf(-lav.z));
    a.w = 1.0f / (1.0f + expf(-lav.w));
    a.x = fminf(fmaxf(a.x, 1.0e-4f), 1.0f - 1.0e-4f);
    a.y = fminf(fmaxf(a.y, 1.0e-4f), 1.0f - 1.0e-4f);
    a.z = fminf(fmaxf(a.z, 1.0e-4f), 1.0f - 1.0e-4f);
    a.w = fminf(fmaxf(a.w, 1.0e-4f), 1.0f - 1.0e-4f);
    const float4 omb = make_float4(1.f-a.x, 1.f-a.y, 1.f-a.z, 1.f-a.w);

    // A = a^TC via 4 squarings (TC = 16 = 2^4)
    float4 A = a;
#pragma unroll
    for (int k = 0; k < 4; k++) A = f4mul(A, A);

    const size_t base = ((size_t)b * Tn + (size_t)j * TC) * (size_t)ROWS4 + c4;
    const float4* xp = (const float4*)x + base;
    float4*       yp = (float4*)y + base;

    // ---- Pass A: local scan (zero carry-in), 4 independent chains, regs ----
    float4 loc[TC];
    float4 l;
    if (j == 0) {
        l = __ldcs(&xp[0]);           // y[b,0,:] = x[b,0,:] exactly
        loc[0] = l;
#pragma unroll
        for (int i = 1; i < TC; i++) {
            const float4 v = __ldcs(&xp[(size_t)i * ROWS4]);
            l = f4fma(a, l, f4mul(omb, v));
            loc[i] = l;
        }
    } else {
        l = make_float4(0.f, 0.f, 0.f, 0.f);
#pragma unroll
        for (int i = 0; i < TC; i++) {
            const float4 v = __ldcs(&xp[(size_t)i * ROWS4]);
            l = f4fma(a, l, f4mul(omb, v));
            loc[i] = l;
        }
    }

    // ---- Publish aggregate (last chunk's state is never consumed) ----
    if (j < NC - 1) {
        g_L4[(size_t)(b * NC + j) * ROWS4 + c4] = l;
        __threadfence();
        __syncthreads();
        if (threadIdx.x == 0) atomicExch(&g_flag[b * NC + j], ready);
    }

    // ---- Batched lookback: carry = sum_{k>=1} A^(k-1) * L[j-k] ----
    float4 carry = make_float4(0.f, 0.f, 0.f, 0.f);
    if (j > 0) {
        const int K = (j < KMAX) ? j : KMAX;
        // Poll K predecessor flags concurrently (one lane each).
        if ((int)threadIdx.x < K) {
            unsigned int* f = &g_flag[b * NC + (j - 1 - (int)threadIdx.x)];
            while (atomicAdd(f, 0u) < ready) __nanosleep(32);
        }
        __syncthreads();
        __threadfence();   // order flag observation before aggregate reads

        float4 w = make_float4(1.f, 1.f, 1.f, 1.f);
        // K independent L2 loads in flight, then fold.
        float4 Lk[KMAX];
#pragma unroll
        for (int k = 0; k < KMAX; k++) {
            if (k < K)
                Lk[k] = __ldcg(&g_L4[(size_t)(b * NC + (j - 1 - k)) * ROWS4 + c4]);
        }
#pragma unroll
        for (int k = 0; k < KMAX; k++) {
            if (k < K) {
                carry = f4fma(w, Lk[k], carry);
                w = f4mul(w, A);
            }
        }

        // Generic residual walk (unconditional correctness for any alpha):
        // continue until weights vanish or chunk 0 (whose aggregate is exact).
        int p = j - 1 - K;
        float mw = fmaxf(fmaxf(fabsf(w.x), fabsf(w.y)),
                         fmaxf(fabsf(w.z), fabsf(w.w)));
        bool done = __syncthreads_and(mw < 1e-12f);
        while (p >= 0 && !done) {
            if (threadIdx.x == 0) {
                unsigned int* f = &g_flag[b * NC + p];
                while (atomicAdd(f, 0u) < ready) __nanosleep(32);
            }
            __syncthreads();
            __threadfence();
            const float4 L = __ldcg(&g_L4[(size_t)(b * NC + p) * ROWS4 + c4]);
            carry = f4fma(w, L, carry);
            w = f4mul(w, A);
            p--;
            mw = fmaxf(fmaxf(fabsf(w.x), fabsf(w.y)),
                       fmaxf(fabsf(w.z), fabsf(w.w)));
            done = __syncthreads_and(mw < 1e-12f);
        }
    }

    // ---- Pass B: y_i = loc_i + a^(i+1) * carry, streaming stores ----
    if (j == 0) {
#pragma unroll
        for (int i = 0; i < TC; i++) __stcs(&yp[(size_t)i * ROWS4], loc[i]);
    } else {
        float4 w = a;
#pragma unroll
        for (int i = 0; i < TC; i++) {
            __stcs(&yp[(size_t)i * ROWS4], f4fma(w, carry, loc[i]));
            w = f4mul(w, a);
        }
    }
}

extern "C" void kernel_launch(void* const* d_in, const int* in_sizes, int n_in,
                              void* d_out, int out_size) {
    const float* x  = (const float*)d_in[0];
    const float* la = (const float*)d_in[1];
    float*       y  = (float*)d_out;

    ema_scan_kernel<<<NBLK, CB>>>(x, la, y);
}

// round 4
// speedup vs baseline: 1.0475x; 1.0475x over previous
#include <cuda_runtime.h>
#include <cuda_bf16.h>

// LearnableEMA: y[b,0,:] = x[b,0,:]; y[b,t,:] = a*y[b,t-1,:] + (1-a)*x[b,t,:]
// a = clip(sigmoid(logit_alpha), 1e-4, 1-1e-4), per channel.
//
// Decoupled-lookback scan, recompute-from-L2 variant:
//  Pass A: scan chunk (running value only, NO loc[] array), publish aggregate.
//  Lookback: carry = sum_k A^(k-1) * L[j-k], eps-truncated (A = a^TC).
//  Pass B: re-scan the chunk seeded with l = carry (exact recurrence),
//          x re-read hits L2 (touched ~2-5K cycles earlier).
// Registers stay ~45 -> high occupancy -> lookback latency fully overlapped.

#define Bn 16
#define Tn 4096
#define Cn 512
#define TC 32             // chunk length along T
#define NC (Tn / TC)      // 128 chunks
#define CB 128            // threads; each owns 4 channels (float4)
#define NBLK (Bn * NC)    // 2048 blocks
#define ROWS4 (Cn / 4)    // float4s per row = 128
#define KB 10             // batched lookback depth (covers a=0.9: A^10 ~ 2e-15)

// Lookback state (device globals: no allocation allowed).
__device__ float4       g_L4[NBLK * ROWS4];  // chunk aggregates (zero carry-in)
__device__ unsigned int g_flag[NBLK];        // == epoch+1 when aggregate ready
__device__ unsigned int g_ticket;            // monotone across graph replays

__device__ __forceinline__ float4 f4mul(float4 u, float4 v) {
    return make_float4(u.x*v.x, u.y*v.y, u.z*v.z, u.w*v.w);
}
__device__ __forceinline__ float4 f4fma(float4 a, float4 b, float4 c) {
    return make_float4(fmaf(a.x,b.x,c.x), fmaf(a.y,b.y,c.y),
                       fmaf(a.z,b.z,c.z), fmaf(a.w,b.w,c.w));
}

__global__ __launch_bounds__(CB, 8) void ema_scan_kernel(
    const float* __restrict__ x,
    const float* __restrict__ logit_alpha,
    float* __restrict__ y)
{
    __shared__ unsigned int s_raw;

    // Ticket: virtual block id in scheduling order (chunk index outermost)
    // => a block only waits on blocks with earlier tickets (resident/retired).
    if (threadIdx.x == 0) s_raw = atomicAdd(&g_ticket, 1u);
    __syncthreads();
    const unsigned int raw   = s_raw;
    const unsigned int epoch = raw / NBLK;
    const unsigned int vbid  = raw % NBLK;
    const unsigned int ready = epoch + 1u;

    const int j  = (int)(vbid / Bn);   // chunk index (outermost in ticket order)
    const int b  = (int)(vbid % Bn);
    const int c4 = threadIdx.x;        // float4 channel-group index

    // Per-channel alpha (4 channels per thread)
    const float4 lav = ((const float4*)logit_alpha)[c4];
    float4 a;
    a.x = 1.0f / (1.0f + expf(-lav.x));
    a.y = 1.0f / (1.0f + expf(-lav.y));
    a.z = 1.0f / (1.0f + expf(-lav.z));
    a.w = 1.0f / (1.0f + expf(-lav.w));
    a.x = fminf(fmaxf(a.x, 1.0e-4f), 1.0f - 1.0e-4f);
    a.y = fminf(fmaxf(a.y, 1.0e-4f), 1.0f - 1.0e-4f);
    a.z = fminf(fmaxf(a.z, 1.0e-4f), 1.0f - 1.0e-4f);
    a.w = fminf(fmaxf(a.w, 1.0e-4f), 1.0f - 1.0e-4f);
    const float4 omb = make_float4(1.f-a.x, 1.f-a.y, 1.f-a.z, 1.f-a.w);

    // A = a^TC via 5 squarings (TC = 32 = 2^5)
    float4 A = a;
#pragma unroll
    for (int k = 0; k < 5; k++) A = f4mul(A, A);

    const size_t base = ((size_t)b * Tn + (size_t)j * TC) * (size_t)ROWS4 + c4;
    const float4* xp = (const float4*)x + base;
    float4*       yp = (float4*)y + base;

    // ---- Pass A: aggregate only (running value, no loc array) ----
    // Skipped for the last chunk of each sequence (aggregate never consumed).
    if (j < NC - 1) {
        float4 l;
        if (j == 0) {
            l = xp[0];                 // y[b,0,:] = x[b,0,:] exactly
#pragma unroll 8
            for (int i = 1; i < TC; i++) {
                const float4 v = xp[(size_t)i * ROWS4];
                l = f4fma(a, l, f4mul(omb, v));
            }
        } else {
            l = f4mul(omb, xp[0]);
#pragma unroll 8
            for (int i = 1; i < TC; i++) {
                const float4 v = xp[(size_t)i * ROWS4];
                l = f4fma(a, l, f4mul(omb, v));
            }
        }
        g_L4[(size_t)(b * NC + j) * ROWS4 + c4] = l;
        __threadfence();
        __syncthreads();
        if (threadIdx.x == 0) atomicExch(&g_flag[b * NC + j], ready);
    }

    // ---- Lookback: carry = true y at end of chunk j-1 ----
    float4 carry = make_float4(0.f, 0.f, 0.f, 0.f);
    if (j > 0) {
        const int K = (j < KB) ? j : KB;
        // Poll K predecessor flags concurrently (one lane each).
        if ((int)threadIdx.x < K) {
            unsigned int* f = &g_flag[b * NC + (j - 1 - (int)threadIdx.x)];
            while (atomicAdd(f, 0u) < ready) __nanosleep(32);
        }
        __syncthreads();
        __threadfence();   // order flag observation before aggregate reads

        float4 w = make_float4(1.f, 1.f, 1.f, 1.f);
#pragma unroll
        for (int k = 0; k < KB; k++) {
            if (k < K) {
                const float4 L = __ldcg(&g_L4[(size_t)(b * NC + (j - 1 - k)) * ROWS4 + c4]);
                carry = f4fma(w, L, carry);
                w = f4mul(w, A);
            }
        }

        // Generic residual walk (unconditional correctness for any alpha):
        // continue until weights vanish or chunk 0 (whose aggregate is exact).
        int p = j - 1 - K;
        float mw = fmaxf(fmaxf(fabsf(w.x), fabsf(w.y)),
                         fmaxf(fabsf(w.z), fabsf(w.w)));
        bool done = __syncthreads_and(mw < 1e-12f);
        while (p >= 0 && !done) {
            if (threadIdx.x == 0) {
                unsigned int* f = &g_flag[b * NC + p];
                while (atomicAdd(f, 0u) < ready) __nanosleep(32);
            }
            __syncthreads();
            __threadfence();
            const float4 L = __ldcg(&g_L4[(size_t)(b * NC + p) * ROWS4 + c4]);
            carry = f4fma(w, L, carry);
            w = f4mul(w, A);
            p--;
            mw = fmaxf(fmaxf(fabsf(w.x), fabsf(w.y)),
                       fmaxf(fabsf(w.z), fabsf(w.w)));
            done = __syncthreads_and(mw < 1e-12f);
        }
    }

    // ---- Pass B: exact re-scan seeded with carry; x re-read hits L2 ----
    float4 l;
    int i0;
    if (j == 0) {
        l = __ldcs(&xp[0]);
        __stcs(&yp[0], l);
        i0 = 1;
    } else {
        l = carry;
        i0 = 0;
    }
#pragma unroll 8
    for (int i = i0; i < TC; i++) {
        const float4 v = __ldcs(&xp[(size_t)i * ROWS4]);
        l = f4fma(a, l, f4mul(omb, v));
        __stcs(&yp[(size_t)i * ROWS4], l);
    }
}

extern "C" void kernel_launch(void* const* d_in, const int* in_sizes, int n_in,
                              void* d_out, int out_size) {
    const float* x  = (const float*)d_in[0];
    const float* la = (const float*)d_in[1];
    float*       y  = (float*)d_out;

    ema_scan_kernel<<<NBLK, CB>>>(x, la, y);
}